// round 1
// baseline (speedup 1.0000x reference)
#include <cuda_runtime.h>
#include <math.h>

#define H    1024
#define NH   16
#define NKV  8
#define HD   128
#define II   3072
#define MAXS 16
#define LL   5
#define EPS  1e-6f

// Residual / activation scratch (allocation-free: __device__ globals)
__device__ float g_x[H];
__device__ float g_qraw[NH * HD];
__device__ float g_kraw[NKV * HD];
__device__ float g_vraw[NKV * HD];
__device__ float g_attn[NH * HD];
__device__ float g_t[II];

__device__ __forceinline__ float warp_sum(float v) {
#pragma unroll
    for (int o = 16; o; o >>= 1) v += __shfl_xor_sync(0xffffffffu, v, o);
    return v;
}

__global__ void init_x(const float* __restrict__ hs) {
    g_x[threadIdx.x] = hs[threadIdx.x];
}

// ---------------------------------------------------------------------------
// QKV: h = rms(x, w_iln); q/k/v = W @ h.  4096 rows total, warp per row.
// grid 512 x 256
// ---------------------------------------------------------------------------
__global__ void qkv_kernel(const float* __restrict__ wiln,
                           const float* __restrict__ wq,
                           const float* __restrict__ wk,
                           const float* __restrict__ wv) {
    __shared__ float h[H];
    __shared__ float red[8];
    int tid = threadIdx.x;
    float xv[4];
    float ssq = 0.f;
#pragma unroll
    for (int i = 0; i < 4; i++) { xv[i] = g_x[tid + i * 256]; ssq += xv[i] * xv[i]; }
    ssq = warp_sum(ssq);
    if ((tid & 31) == 0) red[tid >> 5] = ssq;
    __syncthreads();
    float tot = 0.f;
#pragma unroll
    for (int i = 0; i < 8; i++) tot += red[i];
    float inv = rsqrtf(tot * (1.f / H) + EPS);
#pragma unroll
    for (int i = 0; i < 4; i++) h[tid + i * 256] = xv[i] * inv * wiln[tid + i * 256];
    __syncthreads();

    int warp = tid >> 5, lane = tid & 31;
    int row = blockIdx.x * 8 + warp;
    const float* wrow;
    float* outp;
    if (row < NH * HD)               { wrow = wq + (size_t)row * H;                  outp = g_qraw + row; }
    else if (row < NH * HD + NKV * HD) { int r = row - NH * HD; wrow = wk + (size_t)r * H; outp = g_kraw + r; }
    else                             { int r = row - NH * HD - NKV * HD; wrow = wv + (size_t)r * H; outp = g_vraw + r; }

    const float4* w4 = (const float4*)wrow;
    const float4* h4 = (const float4*)h;
    float acc = 0.f;
#pragma unroll
    for (int j = 0; j < 8; j++) {
        float4 a = w4[lane + j * 32];
        float4 b = h4[lane + j * 32];
        acc += a.x * b.x + a.y * b.y + a.z * b.z + a.w * b.w;
    }
    acc = warp_sum(acc);
    if (lane == 0) *outp = acc;
}

// ---------------------------------------------------------------------------
// Attention: q/k norm + RoPE + cache write + softmax-attn.  1 block x 256.
// warp w handles kv head w and q heads 2w, 2w+1 (all warp-local data).
// ---------------------------------------------------------------------------
__global__ void attn_kernel(const int* __restrict__ pos_p,
                            const float* __restrict__ w_qn,
                            const float* __restrict__ w_kn,
                            const float* __restrict__ past_k,  // layer base [NKV,MAXS,HD]
                            const float* __restrict__ past_v,
                            float* __restrict__ out_k,         // layer base into d_out cache
                            float* __restrict__ out_v) {
    __shared__ float qs[NH * HD];
    __shared__ float ks[NKV * HD];
    __shared__ float vs[NKV * HD];
    __shared__ float sc[NH][MAXS];
    int tid = threadIdx.x, warp = tid >> 5, lane = tid & 31;
    int pos = pos_p[0];

    // RoPE coefficients for this lane's 4 dims: d = lane, lane+32, lane+64, lane+96
    // cos/sin index = d % 64; pairs (lane, lane+64) and (lane+32, lane+96)
    const float NEG_LN_THETA_OVER_64 = -13.815510557964274f / 64.f;  // -ln(1e6)/64
    float f0 = (float)pos * expf((float)lane * NEG_LN_THETA_OVER_64);
    float f1 = (float)pos * expf((float)(lane + 32) * NEG_LN_THETA_OVER_64);
    float c0 = cosf(f0), s0 = sinf(f0), c1 = cosf(f1), s1 = sinf(f1);

    // --- K: rms(w_kn) + rope; V passthrough; write new cache entry ---
    {
        int kvh = warp;  // 8 warps == 8 kv heads
        const float* kr = g_kraw + kvh * HD;
        float r0 = kr[lane], r1 = kr[lane + 32], r2 = kr[lane + 64], r3 = kr[lane + 96];
        float ssq = warp_sum(r0 * r0 + r1 * r1 + r2 * r2 + r3 * r3);
        float inv = rsqrtf(ssq * (1.f / HD) + EPS);
        float k0 = r0 * inv * w_kn[lane];
        float k1 = r1 * inv * w_kn[lane + 32];
        float k2 = r2 * inv * w_kn[lane + 64];
        float k3 = r3 * inv * w_kn[lane + 96];
        float o0 = k0 * c0 - k2 * s0;
        float o2 = k2 * c0 + k0 * s0;
        float o1 = k1 * c1 - k3 * s1;
        float o3 = k3 * c1 + k1 * s1;
        float* kd = ks + kvh * HD;
        kd[lane] = o0; kd[lane + 32] = o1; kd[lane + 64] = o2; kd[lane + 96] = o3;
        float* okp = out_k + (size_t)(kvh * MAXS + pos) * HD;
        okp[lane] = o0; okp[lane + 32] = o1; okp[lane + 64] = o2; okp[lane + 96] = o3;

        const float* vr = g_vraw + kvh * HD;
        float v0 = vr[lane], v1 = vr[lane + 32], v2 = vr[lane + 64], v3 = vr[lane + 96];
        float* vd = vs + kvh * HD;
        vd[lane] = v0; vd[lane + 32] = v1; vd[lane + 64] = v2; vd[lane + 96] = v3;
        float* ovp = out_v + (size_t)(kvh * MAXS + pos) * HD;
        ovp[lane] = v0; ovp[lane + 32] = v1; ovp[lane + 64] = v2; ovp[lane + 96] = v3;
    }

    // --- Q: rms(w_qn) + rope ---
#pragma unroll
    for (int hh = 0; hh < 2; hh++) {
        int hq = warp * 2 + hh;
        const float* qr = g_qraw + hq * HD;
        float r0 = qr[lane], r1 = qr[lane + 32], r2 = qr[lane + 64], r3 = qr[lane + 96];
        float ssq = warp_sum(r0 * r0 + r1 * r1 + r2 * r2 + r3 * r3);
        float inv = rsqrtf(ssq * (1.f / HD) + EPS);
        float q0 = r0 * inv * w_qn[lane];
        float q1 = r1 * inv * w_qn[lane + 32];
        float q2 = r2 * inv * w_qn[lane + 64];
        float q3 = r3 * inv * w_qn[lane + 96];
        float* qd = qs + hq * HD;
        qd[lane]      = q0 * c0 - q2 * s0;
        qd[lane + 64] = q2 * c0 + q0 * s0;
        qd[lane + 32] = q1 * c1 - q3 * s1;
        qd[lane + 96] = q3 * c1 + q1 * s1;
    }
    __syncthreads();

    const float scale = 0.08838834764831845f;  // 1/sqrt(128)
#pragma unroll
    for (int hh = 0; hh < 2; hh++) {
        int hq = warp * 2 + hh;
        int kvh = hq >> 1;
        const float* qd = qs + hq * HD;
        float q0 = qd[lane], q1 = qd[lane + 32], q2 = qd[lane + 64], q3 = qd[lane + 96];
        for (int t = 0; t <= pos; t++) {
            const float* kt = (t == pos) ? (ks + kvh * HD)
                                         : (past_k + (size_t)(kvh * MAXS + t) * HD);
            float p = q0 * kt[lane] + q1 * kt[lane + 32] + q2 * kt[lane + 64] + q3 * kt[lane + 96];
            p = warp_sum(p);
            if (lane == 0) sc[hq][t] = p;
        }
        __syncwarp();
        float v = (lane <= pos) ? sc[hq][lane] * scale : -INFINITY;
        float m = v;
#pragma unroll
        for (int o = 16; o; o >>= 1) m = fmaxf(m, __shfl_xor_sync(0xffffffffu, m, o));
        float e = (lane <= pos) ? expf(v - m) : 0.f;
        float sum = warp_sum(e);
        float p = e / sum;
        float a0 = 0.f, a1 = 0.f, a2 = 0.f, a3 = 0.f;
        for (int t = 0; t <= pos; t++) {
            float pt = __shfl_sync(0xffffffffu, p, t);
            const float* vt = (t == pos) ? (vs + kvh * HD)
                                         : (past_v + (size_t)(kvh * MAXS + t) * HD);
            a0 += pt * vt[lane]; a1 += pt * vt[lane + 32];
            a2 += pt * vt[lane + 64]; a3 += pt * vt[lane + 96];
        }
        float* ad = g_attn + hq * HD;
        ad[lane] = a0; ad[lane + 32] = a1; ad[lane + 64] = a2; ad[lane + 96] = a3;
    }
}

// ---------------------------------------------------------------------------
// O projection + residual: x += wo @ attn.  1024 rows x 2048.  grid 128 x 256
// ---------------------------------------------------------------------------
__global__ void o_kernel(const float* __restrict__ wo) {
    __shared__ float s[NH * HD];
    int tid = threadIdx.x;
#pragma unroll
    for (int i = 0; i < 8; i++) s[tid + i * 256] = g_attn[tid + i * 256];
    __syncthreads();
    int warp = tid >> 5, lane = tid & 31;
    int row = blockIdx.x * 8 + warp;
    const float4* w4 = (const float4*)(wo + (size_t)row * (NH * HD));
    const float4* a4 = (const float4*)s;
    float acc = 0.f;
#pragma unroll
    for (int j = 0; j < 16; j++) {
        float4 a = w4[lane + j * 32];
        float4 b = a4[lane + j * 32];
        acc += a.x * b.x + a.y * b.y + a.z * b.z + a.w * b.w;
    }
    acc = warp_sum(acc);
    if (lane == 0) g_x[row] += acc;
}

// ---------------------------------------------------------------------------
// Gate/Up: h = rms(x, w_paln); t = silu(wg@h) * (wu@h).  3072 rows, warp/row.
// grid 384 x 256
// ---------------------------------------------------------------------------
__global__ void gu_kernel(const float* __restrict__ wpaln,
                          const float* __restrict__ wg,
                          const float* __restrict__ wu) {
    __shared__ float h[H];
    __shared__ float red[8];
    int tid = threadIdx.x;
    float xv[4];
    float ssq = 0.f;
#pragma unroll
    for (int i = 0; i < 4; i++) { xv[i] = g_x[tid + i * 256]; ssq += xv[i] * xv[i]; }
    ssq = warp_sum(ssq);
    if ((tid & 31) == 0) red[tid >> 5] = ssq;
    __syncthreads();
    float tot = 0.f;
#pragma unroll
    for (int i = 0; i < 8; i++) tot += red[i];
    float inv = rsqrtf(tot * (1.f / H) + EPS);
#pragma unroll
    for (int i = 0; i < 4; i++) h[tid + i * 256] = xv[i] * inv * wpaln[tid + i * 256];
    __syncthreads();

    int warp = tid >> 5, lane = tid & 31;
    int row = blockIdx.x * 8 + warp;
    const float4* g4 = (const float4*)(wg + (size_t)row * H);
    const float4* u4 = (const float4*)(wu + (size_t)row * H);
    const float4* h4 = (const float4*)h;
    float ag = 0.f, au = 0.f;
#pragma unroll
    for (int j = 0; j < 8; j++) {
        float4 b = h4[lane + j * 32];
        float4 a = g4[lane + j * 32];
        ag += a.x * b.x + a.y * b.y + a.z * b.z + a.w * b.w;
        float4 c = u4[lane + j * 32];
        au += c.x * b.x + c.y * b.y + c.z * b.z + c.w * b.w;
    }
    ag = warp_sum(ag);
    au = warp_sum(au);
    if (lane == 0) {
        float sg = ag / (1.f + expf(-ag));  // silu
        g_t[row] = sg * au;
    }
}

// ---------------------------------------------------------------------------
// Down + residual: x += wd @ t.  1024 rows x 3072.  grid 128 x 256
// ---------------------------------------------------------------------------
__global__ void down_kernel(const float* __restrict__ wd) {
    __shared__ float s[II];
    int tid = threadIdx.x;
#pragma unroll
    for (int i = 0; i < 12; i++) s[tid + i * 256] = g_t[tid + i * 256];
    __syncthreads();
    int warp = tid >> 5, lane = tid & 31;
    int row = blockIdx.x * 8 + warp;
    const float4* w4 = (const float4*)(wd + (size_t)row * II);
    const float4* t4 = (const float4*)s;
    float acc = 0.f;
#pragma unroll
    for (int j = 0; j < 24; j++) {
        float4 a = w4[lane + j * 32];
        float4 b = t4[lane + j * 32];
        acc += a.x * b.x + a.y * b.y + a.z * b.z + a.w * b.w;
    }
    acc = warp_sum(acc);
    if (lane == 0) g_x[row] += acc;
}

// ---------------------------------------------------------------------------
// Final: out = rms(x, w_onorm).  1 block x 256
// ---------------------------------------------------------------------------
__global__ void final_kernel(const float* __restrict__ wonorm, float* __restrict__ out) {
    __shared__ float red[8];
    int tid = threadIdx.x;
    float xv[4];
    float ssq = 0.f;
#pragma unroll
    for (int i = 0; i < 4; i++) { xv[i] = g_x[tid + i * 256]; ssq += xv[i] * xv[i]; }
    ssq = warp_sum(ssq);
    if ((tid & 31) == 0) red[tid >> 5] = ssq;
    __syncthreads();
    float tot = 0.f;
#pragma unroll
    for (int i = 0; i < 8; i++) tot += red[i];
    float inv = rsqrtf(tot * (1.f / H) + EPS);
#pragma unroll
    for (int i = 0; i < 4; i++) out[tid + i * 256] = xv[i] * inv * wonorm[tid + i * 256];
}

extern "C" void kernel_launch(void* const* d_in, const int* in_sizes, int n_in,
                              void* d_out, int out_size) {
    const float* hs     = (const float*)d_in[0];
    const int*   pos    = (const int*)d_in[1];
    const float* pk     = (const float*)d_in[2];
    const float* pv     = (const float*)d_in[3];
    const float* wiln   = (const float*)d_in[4];
    const float* wpaln  = (const float*)d_in[5];
    const float* wq     = (const float*)d_in[6];
    const float* wk     = (const float*)d_in[7];
    const float* wv     = (const float*)d_in[8];
    const float* wo     = (const float*)d_in[9];
    const float* wqn    = (const float*)d_in[10];
    const float* wkn    = (const float*)d_in[11];
    const float* wg     = (const float*)d_in[12];
    const float* wu     = (const float*)d_in[13];
    const float* wd     = (const float*)d_in[14];
    const float* wonorm = (const float*)d_in[15];

    float* out   = (float*)d_out;
    float* out_k = out + H;
    float* out_v = out_k + (size_t)LL * NKV * MAXS * HD;

    const size_t cache_bytes = (size_t)LL * NKV * MAXS * HD * sizeof(float);
    cudaMemcpyAsync(out_k, pk, cache_bytes, cudaMemcpyDeviceToDevice, 0);
    cudaMemcpyAsync(out_v, pv, cache_bytes, cudaMemcpyDeviceToDevice, 0);

    init_x<<<1, 1024>>>(hs);

    for (int l = 0; l < LL; l++) {
        size_t lofs = (size_t)l * NKV * MAXS * HD;
        qkv_kernel<<<512, 256>>>(wiln + l * H,
                                 wq + (size_t)l * NH * HD * H,
                                 wk + (size_t)l * NKV * HD * H,
                                 wv + (size_t)l * NKV * HD * H);
        attn_kernel<<<1, 256>>>(pos, wqn + l * HD, wkn + l * HD,
                                pk + lofs, pv + lofs,
                                out_k + lofs, out_v + lofs);
        o_kernel<<<128, 256>>>(wo + (size_t)l * H * NH * HD);
        gu_kernel<<<384, 256>>>(wpaln + l * H,
                                wg + (size_t)l * II * H,
                                wu + (size_t)l * II * H);
        down_kernel<<<128, 256>>>(wd + (size_t)l * H * II);
    }
    final_kernel<<<1, 256>>>(wonorm, out);
}